// round 12
// baseline (speedup 1.0000x reference)
#include <cuda_runtime.h>
#include <math.h>

#define D 128
#define MAXN 100000
#define MAXR 64
#define MAXE 600000
#define SCAN_B 1024
#define MAXBLK 128
#define IDXBITS 17
#define IDXMASK ((1u << IDXBITS) - 1u)

// ---- device-global scratch (alloc-free rule) ----
__device__ float    g_V[MAXR * 2 * D];
__device__ float    g_scr_u[(size_t)MAXN * D];
__device__ float    g_scr_i[(size_t)MAXN * D];
__device__ int      g_deg_u[MAXN], g_deg_i[MAXN];
__device__ int      g_off_u[MAXN + 1], g_off_i[MAXN + 1];
__device__ int      g_cur_u[MAXN], g_cur_i[MAXN];
__device__ int      g_part_u[MAXBLK], g_part_i[MAXBLK];
__device__ unsigned g_adj_u[MAXE];     // packed: idx | (rel << IDXBITS)
__device__ unsigned g_adj_i[MAXE];

// Blocks < R compute V[r]; all blocks zero degree arrays.
__global__ void compute_V_init(const float* __restrict__ W,
                               const float* __restrict__ rel,
                               int R, int Nu, int Ne) {
    if (blockIdx.x < R) {
        __shared__ float srel[D];
        int r = blockIdx.x, j = threadIdx.x;
        if (j < D) srel[j] = rel[r * D + j];
        __syncthreads();
        float acc = 0.f;
#pragma unroll 8
        for (int k = 0; k < D; k++) acc = fmaf(W[j * D + k], srel[k], acc);
        g_V[r * 2 * D + j] = acc;
    }
    int idx = blockIdx.x * blockDim.x + threadIdx.x;
    int T = gridDim.x * blockDim.x;
    for (int k = idx; k < Nu; k += T) g_deg_u[k] = 0;
    for (int k = idx; k < Ne; k += T) g_deg_i[k] = 0;
}

__global__ void hist_kernel(const int* __restrict__ head,
                            const int* __restrict__ tail, int E) {
    int i = blockIdx.x * blockDim.x + threadIdx.x;
    if (i < E) {
        atomicAdd(g_deg_u + head[i], 1);
        atomicAdd(g_deg_i + tail[i], 1);
    }
}

__global__ void scan_partial(int Nu, int Ne, int nblk_u) {
    int b = blockIdx.x;
    const int* deg; int* part; int N, lb;
    if (b < nblk_u) { deg = g_deg_u; part = g_part_u; N = Nu; lb = b; }
    else            { deg = g_deg_i; part = g_part_i; N = Ne; lb = b - nblk_u; }
    int tid = threadIdx.x, lane = tid & 31, wid = tid >> 5;
    int i = lb * SCAN_B + tid;
    int v = (i < N) ? deg[i] : 0;
    __shared__ int wsum[32];
#pragma unroll
    for (int o = 16; o; o >>= 1) v += __shfl_xor_sync(0xffffffffu, v, o);
    if (lane == 0) wsum[wid] = v;
    __syncthreads();
    if (wid == 0) {
        int s = wsum[lane];
#pragma unroll
        for (int o = 16; o; o >>= 1) s += __shfl_xor_sync(0xffffffffu, s, o);
        if (lane == 0) part[lb] = s;
    }
}

__global__ void scan_final(int Nu, int Ne, int nblk_u, int nblk_i) {
    int b = blockIdx.x;
    const int* deg; const int* part; int* off; int* cur; int N, lb, nblk;
    if (b < nblk_u) { deg = g_deg_u; part = g_part_u; off = g_off_u; cur = g_cur_u;
                      N = Nu; lb = b; nblk = nblk_u; }
    else            { deg = g_deg_i; part = g_part_i; off = g_off_i; cur = g_cur_i;
                      N = Ne; lb = b - nblk_u; nblk = nblk_i; }
    int tid = threadIdx.x, lane = tid & 31, wid = tid >> 5;
    __shared__ int s_carry, s_total;
    __shared__ int wsum[32];
    if (wid == 0) {
        int c = 0, t = 0;
        for (int j = lane; j < nblk; j += 32) {
            int p = part[j];
            t += p;
            if (j < lb) c += p;
        }
#pragma unroll
        for (int o = 16; o; o >>= 1) {
            c += __shfl_xor_sync(0xffffffffu, c, o);
            t += __shfl_xor_sync(0xffffffffu, t, o);
        }
        if (lane == 0) { s_carry = c; s_total = t; }
    }
    __syncthreads();
    int i = lb * SCAN_B + tid;
    int v = (i < N) ? deg[i] : 0;
    int x = v;
#pragma unroll
    for (int o = 1; o < 32; o <<= 1) {
        int y = __shfl_up_sync(0xffffffffu, x, o);
        if (lane >= o) x += y;
    }
    if (lane == 31) wsum[wid] = x;
    __syncthreads();
    if (wid == 0) {
        int s = wsum[lane];
#pragma unroll
        for (int o = 1; o < 32; o <<= 1) {
            int y = __shfl_up_sync(0xffffffffu, s, o);
            if (lane >= o) s += y;
        }
        wsum[lane] = s;
    }
    __syncthreads();
    int incl = x + (wid ? wsum[wid - 1] : 0);
    int excl = incl - v + s_carry;
    if (i < N) { off[i] = excl; cur[i] = excl; }
    if (lb == 0 && tid == 0) off[N] = s_total;
}

__global__ void scatter_kernel(const int* __restrict__ head,
                               const int* __restrict__ tail,
                               const int* __restrict__ etype, int E) {
    int i = blockIdx.x * blockDim.x + threadIdx.x;
    if (i < E) {
        int h = head[i], t = tail[i];
        unsigned rbits = ((unsigned)etype[i]) << IDXBITS;
        g_adj_u[atomicAdd(g_cur_u + h, 1)] = (unsigned)t | rbits;
        g_adj_i[atomicAdd(g_cur_i + t, 1)] = (unsigned)h | rbits;
    }
}

// Fused both-sides hop kernel (round-11 loop body, INTERLEAVED side mapping:
// even block -> u-node, odd block -> i-node, so both gather tables are hit
// concurrently throughout execution).
__global__ __launch_bounds__(256)
void agg2_kernel(const float* __restrict__ usr, const float* __restrict__ ent,
                 float* __restrict__ usr_o, float* __restrict__ ent_o,
                 int Nu, int Ne, int gu, int gi) {
    int b = blockIdx.x;
    int m = 2 * min(gu, gi);
    int side, nb;
    if (b < m) { side = b & 1; nb = b >> 1; }
    else       { side = (gu > gi) ? 0 : 1; nb = min(gu, gi) + (b - m); }

    const float* self; const float* other; float* dst;
    const int* off; const unsigned* adj; int N, voff_own, voff_oth;
    if (side == 0) { self = usr; other = ent; dst = usr_o; off = g_off_u;
                     adj = g_adj_u; N = Nu; voff_own = 0; voff_oth = D; }
    else           { self = ent; other = usr; dst = ent_o; off = g_off_i;
                     adj = g_adj_i; N = Ne; voff_own = D; voff_oth = 0; }
    int wid = threadIdx.x >> 5, lane = threadIdx.x & 31;
    int node = nb * 8 + wid;
    if (node >= N) return;

    int beg = off[node];
    int n = off[node + 1] - beg;
    float4 own = __ldcs((const float4*)(self + (size_t)node * D) + lane);
    float4 num = make_float4(0.f, 0.f, 0.f, 0.f);
    float den = 0.f;

    // depth-2 pipeline over edges (adj + oth row only)
    unsigned ad0 = 0, ad1 = 0; float4 o0, o1;
    if (n > 0) {
        ad0 = __ldg(adj + beg);
        o0 = __ldg((const float4*)(other + (size_t)(ad0 & IDXMASK) * D) + lane);
    }
    if (n > 1) {
        ad1 = __ldg(adj + beg + 1);
        o1 = __ldg((const float4*)(other + (size_t)(ad1 & IDXMASK) * D) + lane);
    }
    for (int e = 0; e < n; e++) {
        unsigned ad = ad0; float4 oth = o0;
        ad0 = ad1; o0 = o1;
        if (e + 2 < n) {
            ad1 = __ldg(adj + beg + e + 2);
            o1 = __ldg((const float4*)(other + (size_t)(ad1 & IDXMASK) * D) + lane);
        }
        int r = ad >> IDXBITS;
        float4 vo = __ldg((const float4*)(g_V + r * 2 * D + voff_own) + lane);
        float4 vw = __ldg((const float4*)(g_V + r * 2 * D + voff_oth) + lane);
        float p = own.x * vo.x + own.y * vo.y + own.z * vo.z + own.w * vo.w
                + oth.x * vw.x + oth.y * vw.y + oth.z * vw.z + oth.w * vw.w;
#pragma unroll
        for (int o = 16; o; o >>= 1) p += __shfl_xor_sync(0xffffffffu, p, o);
        float s = p > 0.f ? p : 0.2f * p;            // LeakyReLU(0.2)
        float ee = __expf(s);
        num.x = fmaf(oth.x, ee, num.x);
        num.y = fmaf(oth.y, ee, num.y);
        num.z = fmaf(oth.z, ee, num.z);
        num.w = fmaf(oth.w, ee, num.w);
        den += ee;
    }
    float inv = den > 0.f ? 1.f / den : 0.f;
    float4 a;
    a.x = fmaf(num.x, inv, own.x);
    a.y = fmaf(num.y, inv, own.y);
    a.z = fmaf(num.z, inv, own.z);
    a.w = fmaf(num.w, inv, own.w);
    float ss = a.x * a.x + a.y * a.y + a.z * a.z + a.w * a.w;
#pragma unroll
    for (int o = 16; o; o >>= 1) ss += __shfl_xor_sync(0xffffffffu, ss, o);
    float sc = 1.f / fmaxf(sqrtf(ss), 1e-8f);
    float4 out;
    out.x = fmaf(a.x, sc, own.x);
    out.y = fmaf(a.y, sc, own.y);
    out.z = fmaf(a.z, sc, own.z);
    out.w = fmaf(a.w, sc, own.w);
    __stcs((float4*)(dst + (size_t)node * D) + lane, out);
}

extern "C" void kernel_launch(void* const* d_in, const int* in_sizes, int n_in,
                              void* d_out, int out_size) {
    const float* usr_in = (const float*)d_in[0];
    const float* rel    = (const float*)d_in[1];
    const float* ent_in = (const float*)d_in[2];
    const float* W      = (const float*)d_in[3];
    const int*   eidx   = (const int*)d_in[4];
    const int*   etype  = (const int*)d_in[5];

    int Nu = in_sizes[0] / D;
    int R  = in_sizes[1] / D;
    int Ne = in_sizes[2] / D;
    int E  = in_sizes[5];

    float* usr_out = (float*)d_out;
    float* ent_out = usr_out + (size_t)Nu * D;

    void *p_su, *p_si;
    cudaGetSymbolAddress(&p_su, g_scr_u);
    cudaGetSymbolAddress(&p_si, g_scr_i);
    float* scr_u = (float*)p_su;
    float* scr_i = (float*)p_si;

    const int* head = eidx;
    const int* tail = eidx + E;

    int nblk_u = (Nu + SCAN_B - 1) / SCAN_B;
    int nblk_i = (Ne + SCAN_B - 1) / SCAN_B;
    int gu = (Nu + 7) / 8, gi = (Ne + 7) / 8;

    compute_V_init<<<1024, 2 * D>>>(W, rel, R, Nu, Ne);
    hist_kernel<<<(E + 255) / 256, 256>>>(head, tail, E);
    scan_partial<<<nblk_u + nblk_i, SCAN_B>>>(Nu, Ne, nblk_u);
    scan_final<<<nblk_u + nblk_i, SCAN_B>>>(Nu, Ne, nblk_u, nblk_i);
    scatter_kernel<<<(E + 255) / 256, 256>>>(head, tail, etype, E);

    agg2_kernel<<<gu + gi, 256>>>(usr_in, ent_in, scr_u, scr_i, Nu, Ne, gu, gi);
    agg2_kernel<<<gu + gi, 256>>>(scr_u, scr_i, usr_out, ent_out, Nu, Ne, gu, gi);
}

// round 13
// speedup vs baseline: 1.0761x; 1.0761x over previous
#include <cuda_runtime.h>
#include <math.h>

#define D 128
#define MAXN 100000
#define MAXR 64
#define MAXE 600000
#define SCAN_B 1024
#define MAXBLK 128
#define IDXBITS 17
#define IDXMASK ((1u << IDXBITS) - 1u)

// ---- device-global scratch (alloc-free rule) ----
__device__ float    g_V[MAXR * 2 * D];
__device__ float    g_scr_u[(size_t)MAXN * D];
__device__ float    g_scr_i[(size_t)MAXN * D];
__device__ float    g_esc[MAXE];                   // e_exp in i-CSR order
__device__ int      g_deg_u[MAXN], g_deg_i[MAXN];
__device__ int      g_off_u[MAXN + 1], g_off_i[MAXN + 1];
__device__ int      g_cur_u[MAXN], g_cur_i[MAXN];
__device__ int      g_part_u[MAXBLK], g_part_i[MAXBLK];
__device__ int2     g_adj_u[MAXE];                 // (t | rel<<17, ipos)
__device__ int      g_adj_i[MAXE];                 // h

// Blocks < R compute V[r]; all blocks zero degree arrays.
__global__ void compute_V_init(const float* __restrict__ W,
                               const float* __restrict__ rel,
                               int R, int Nu, int Ne) {
    if (blockIdx.x < R) {
        __shared__ float srel[D];
        int r = blockIdx.x, j = threadIdx.x;
        if (j < D) srel[j] = rel[r * D + j];
        __syncthreads();
        float acc = 0.f;
#pragma unroll 8
        for (int k = 0; k < D; k++) acc = fmaf(W[j * D + k], srel[k], acc);
        g_V[r * 2 * D + j] = acc;
    }
    int idx = blockIdx.x * blockDim.x + threadIdx.x;
    int T = gridDim.x * blockDim.x;
    for (int k = idx; k < Nu; k += T) g_deg_u[k] = 0;
    for (int k = idx; k < Ne; k += T) g_deg_i[k] = 0;
}

__global__ void hist_kernel(const int* __restrict__ head,
                            const int* __restrict__ tail, int E) {
    int i = blockIdx.x * blockDim.x + threadIdx.x;
    if (i < E) {
        atomicAdd(g_deg_u + head[i], 1);
        atomicAdd(g_deg_i + tail[i], 1);
    }
}

__global__ void scan_partial(int Nu, int Ne, int nblk_u) {
    int b = blockIdx.x;
    const int* deg; int* part; int N, lb;
    if (b < nblk_u) { deg = g_deg_u; part = g_part_u; N = Nu; lb = b; }
    else            { deg = g_deg_i; part = g_part_i; N = Ne; lb = b - nblk_u; }
    int tid = threadIdx.x, lane = tid & 31, wid = tid >> 5;
    int i = lb * SCAN_B + tid;
    int v = (i < N) ? deg[i] : 0;
    __shared__ int wsum[32];
#pragma unroll
    for (int o = 16; o; o >>= 1) v += __shfl_xor_sync(0xffffffffu, v, o);
    if (lane == 0) wsum[wid] = v;
    __syncthreads();
    if (wid == 0) {
        int s = wsum[lane];
#pragma unroll
        for (int o = 16; o; o >>= 1) s += __shfl_xor_sync(0xffffffffu, s, o);
        if (lane == 0) part[lb] = s;
    }
}

__global__ void scan_final(int Nu, int Ne, int nblk_u, int nblk_i) {
    int b = blockIdx.x;
    const int* deg; const int* part; int* off; int* cur; int N, lb, nblk;
    if (b < nblk_u) { deg = g_deg_u; part = g_part_u; off = g_off_u; cur = g_cur_u;
                      N = Nu; lb = b; nblk = nblk_u; }
    else            { deg = g_deg_i; part = g_part_i; off = g_off_i; cur = g_cur_i;
                      N = Ne; lb = b - nblk_u; nblk = nblk_i; }
    int tid = threadIdx.x, lane = tid & 31, wid = tid >> 5;
    __shared__ int s_carry, s_total;
    __shared__ int wsum[32];
    if (wid == 0) {
        int c = 0, t = 0;
        for (int j = lane; j < nblk; j += 32) {
            int p = part[j];
            t += p;
            if (j < lb) c += p;
        }
#pragma unroll
        for (int o = 16; o; o >>= 1) {
            c += __shfl_xor_sync(0xffffffffu, c, o);
            t += __shfl_xor_sync(0xffffffffu, t, o);
        }
        if (lane == 0) { s_carry = c; s_total = t; }
    }
    __syncthreads();
    int i = lb * SCAN_B + tid;
    int v = (i < N) ? deg[i] : 0;
    int x = v;
#pragma unroll
    for (int o = 1; o < 32; o <<= 1) {
        int y = __shfl_up_sync(0xffffffffu, x, o);
        if (lane >= o) x += y;
    }
    if (lane == 31) wsum[wid] = x;
    __syncthreads();
    if (wid == 0) {
        int s = wsum[lane];
#pragma unroll
        for (int o = 1; o < 32; o <<= 1) {
            int y = __shfl_up_sync(0xffffffffu, s, o);
            if (lane >= o) s += y;
        }
        wsum[lane] = s;
    }
    __syncthreads();
    int incl = x + (wid ? wsum[wid - 1] : 0);
    int excl = incl - v + s_carry;
    if (i < N) { off[i] = excl; cur[i] = excl; }
    if (lb == 0 && tid == 0) off[N] = s_total;
}

__global__ void scatter_kernel(const int* __restrict__ head,
                               const int* __restrict__ tail,
                               const int* __restrict__ etype, int E) {
    int i = blockIdx.x * blockDim.x + threadIdx.x;
    if (i < E) {
        int h = head[i], t = tail[i], r = etype[i];
        int pu = atomicAdd(g_cur_u + h, 1);
        int pi = atomicAdd(g_cur_i + t, 1);
        g_adj_u[pu] = make_int2((int)((unsigned)t | ((unsigned)r << IDXBITS)), pi);
        g_adj_i[pi] = h;
    }
}

// u-side hop: full score computation (r11 depth-2 loop) + scatter e_exp to
// the edge's i-CSR slot for the lean i-pass.
__global__ __launch_bounds__(256)
void agg_u_kernel(const float* __restrict__ self,
                  const float* __restrict__ other,
                  float* __restrict__ dst, int N) {
    int node = (blockIdx.x * blockDim.x + threadIdx.x) >> 5;
    int lane = threadIdx.x & 31;
    if (node >= N) return;

    int beg = g_off_u[node];
    int n = g_off_u[node + 1] - beg;
    float4 own = __ldcs((const float4*)(self + (size_t)node * D) + lane);
    float4 num = make_float4(0.f, 0.f, 0.f, 0.f);
    float den = 0.f;

    int2 ad0 = make_int2(0, 0), ad1 = make_int2(0, 0); float4 o0, o1;
    if (n > 0) {
        ad0 = __ldg(g_adj_u + beg);
        o0 = __ldg((const float4*)(other + (size_t)(ad0.x & IDXMASK) * D) + lane);
    }
    if (n > 1) {
        ad1 = __ldg(g_adj_u + beg + 1);
        o1 = __ldg((const float4*)(other + (size_t)(ad1.x & IDXMASK) * D) + lane);
    }
    for (int e = 0; e < n; e++) {
        int2 ad = ad0; float4 oth = o0;
        ad0 = ad1; o0 = o1;
        if (e + 2 < n) {
            ad1 = __ldg(g_adj_u + beg + e + 2);
            o1 = __ldg((const float4*)(other + (size_t)(ad1.x & IDXMASK) * D) + lane);
        }
        int r = (unsigned)ad.x >> IDXBITS;
        float4 vo = __ldg((const float4*)(g_V + r * 2 * D) + lane);
        float4 vw = __ldg((const float4*)(g_V + r * 2 * D + D) + lane);
        float p = own.x * vo.x + own.y * vo.y + own.z * vo.z + own.w * vo.w
                + oth.x * vw.x + oth.y * vw.y + oth.z * vw.z + oth.w * vw.w;
#pragma unroll
        for (int o = 16; o; o >>= 1) p += __shfl_xor_sync(0xffffffffu, p, o);
        float s = p > 0.f ? p : 0.2f * p;            // LeakyReLU(0.2)
        float ee = __expf(s);
        if (lane == 0) g_esc[ad.y] = ee;             // forward to i-pass
        num.x = fmaf(oth.x, ee, num.x);
        num.y = fmaf(oth.y, ee, num.y);
        num.z = fmaf(oth.z, ee, num.z);
        num.w = fmaf(oth.w, ee, num.w);
        den += ee;
    }
    float inv = den > 0.f ? 1.f / den : 0.f;
    float4 a;
    a.x = fmaf(num.x, inv, own.x);
    a.y = fmaf(num.y, inv, own.y);
    a.z = fmaf(num.z, inv, own.z);
    a.w = fmaf(num.w, inv, own.w);
    float ss = a.x * a.x + a.y * a.y + a.z * a.z + a.w * a.w;
#pragma unroll
    for (int o = 16; o; o >>= 1) ss += __shfl_xor_sync(0xffffffffu, ss, o);
    float sc = 1.f / fmaxf(sqrtf(ss), 1e-8f);
    float4 out;
    out.x = fmaf(a.x, sc, own.x);
    out.y = fmaf(a.y, sc, own.y);
    out.z = fmaf(a.z, sc, own.z);
    out.w = fmaf(a.w, sc, own.w);
    __stcs((float4*)(dst + (size_t)node * D) + lane, out);
}

// i-side hop (lean): scores precomputed; per edge just idx + score + gather.
__global__ __launch_bounds__(256)
void agg_i_kernel(const float* __restrict__ self,
                  const float* __restrict__ other,
                  float* __restrict__ dst, int N) {
    int node = (blockIdx.x * blockDim.x + threadIdx.x) >> 5;
    int lane = threadIdx.x & 31;
    if (node >= N) return;

    int beg = g_off_i[node];
    int n = g_off_i[node + 1] - beg;
    float4 own = __ldcs((const float4*)(self + (size_t)node * D) + lane);
    float4 num = make_float4(0.f, 0.f, 0.f, 0.f);
    float den = 0.f;

    int i0 = 0, i1 = 0; float4 o0, o1;
    if (n > 0) {
        i0 = __ldg(g_adj_i + beg);
        o0 = __ldg((const float4*)(other + (size_t)i0 * D) + lane);
    }
    if (n > 1) {
        i1 = __ldg(g_adj_i + beg + 1);
        o1 = __ldg((const float4*)(other + (size_t)i1 * D) + lane);
    }
    for (int e = 0; e < n; e++) {
        float4 oth = o0;
        o0 = o1;
        if (e + 2 < n) {
            i1 = __ldg(g_adj_i + beg + e + 2);
            o1 = __ldg((const float4*)(other + (size_t)i1 * D) + lane);
        }
        float ee = __ldg(g_esc + beg + e);
        num.x = fmaf(oth.x, ee, num.x);
        num.y = fmaf(oth.y, ee, num.y);
        num.z = fmaf(oth.z, ee, num.z);
        num.w = fmaf(oth.w, ee, num.w);
        den += ee;
    }
    float inv = den > 0.f ? 1.f / den : 0.f;
    float4 a;
    a.x = fmaf(num.x, inv, own.x);
    a.y = fmaf(num.y, inv, own.y);
    a.z = fmaf(num.z, inv, own.z);
    a.w = fmaf(num.w, inv, own.w);
    float ss = a.x * a.x + a.y * a.y + a.z * a.z + a.w * a.w;
#pragma unroll
    for (int o = 16; o; o >>= 1) ss += __shfl_xor_sync(0xffffffffu, ss, o);
    float sc = 1.f / fmaxf(sqrtf(ss), 1e-8f);
    float4 out;
    out.x = fmaf(a.x, sc, own.x);
    out.y = fmaf(a.y, sc, own.y);
    out.z = fmaf(a.z, sc, own.z);
    out.w = fmaf(a.w, sc, own.w);
    __stcs((float4*)(dst + (size_t)node * D) + lane, out);
}

extern "C" void kernel_launch(void* const* d_in, const int* in_sizes, int n_in,
                              void* d_out, int out_size) {
    const float* usr_in = (const float*)d_in[0];
    const float* rel    = (const float*)d_in[1];
    const float* ent_in = (const float*)d_in[2];
    const float* W      = (const float*)d_in[3];
    const int*   eidx   = (const int*)d_in[4];
    const int*   etype  = (const int*)d_in[5];

    int Nu = in_sizes[0] / D;
    int R  = in_sizes[1] / D;
    int Ne = in_sizes[2] / D;
    int E  = in_sizes[5];

    float* usr_out = (float*)d_out;
    float* ent_out = usr_out + (size_t)Nu * D;

    void *p_su, *p_si;
    cudaGetSymbolAddress(&p_su, g_scr_u);
    cudaGetSymbolAddress(&p_si, g_scr_i);
    float* scr_u = (float*)p_su;
    float* scr_i = (float*)p_si;

    const int* head = eidx;
    const int* tail = eidx + E;

    int nblk_u = (Nu + SCAN_B - 1) / SCAN_B;
    int nblk_i = (Ne + SCAN_B - 1) / SCAN_B;
    int gu = (Nu + 7) / 8, gi = (Ne + 7) / 8;

    compute_V_init<<<1024, 2 * D>>>(W, rel, R, Nu, Ne);
    hist_kernel<<<(E + 255) / 256, 256>>>(head, tail, E);
    scan_partial<<<nblk_u + nblk_i, SCAN_B>>>(Nu, Ne, nblk_u);
    scan_final<<<nblk_u + nblk_i, SCAN_B>>>(Nu, Ne, nblk_u, nblk_i);
    scatter_kernel<<<(E + 255) / 256, 256>>>(head, tail, etype, E);

    // hop 1
    agg_u_kernel<<<gu, 256>>>(usr_in, ent_in, scr_u, Nu);
    agg_i_kernel<<<gi, 256>>>(ent_in, usr_in, scr_i, Ne);
    // hop 2
    agg_u_kernel<<<gu, 256>>>(scr_u, scr_i, usr_out, Nu);
    agg_i_kernel<<<gi, 256>>>(scr_i, scr_u, ent_out, Ne);
}